// round 14
// baseline (speedup 1.0000x reference)
#include <cuda_runtime.h>

#define N_NODES 50000
#define N_EDGES 800000
#define IN_C    64
#define HID_C   128
#define OUT_C   64

// ---------------- scratch (static device globals; no allocation) ----------------
__device__ __align__(16) float g_S1 [N_NODES * IN_C];   // layer-1 aggregate (incl self)
__device__ __align__(16) float g_P  [N_NODES * OUT_C];  // H·W2_j  (message proj)
__device__ __align__(16) float g_Q  [N_NODES * OUT_C];  // H·W2_i  (self proj)
__device__ __align__(16) float g_S2p[N_NODES * OUT_C];  // layer-2 proj-aggregate
__device__ __align__(16) float g_cnt[N_NODES];          // in-degree (float)
__device__ __align__(16) float g_sea[N_NODES];          // scatter-sum of edge_attr
__device__ __align__(16) int   g_idx[2 * N_EDGES];      // [src(E), dst(E)] as int32
__device__ int g_is64;                                  // edge_index dtype flag

// ---------------- helpers ----------------
__device__ __forceinline__ void red_add_v4(float* p, float4 v) {
    asm volatile("red.global.add.v4.f32 [%0], {%1,%2,%3,%4};"
                 :: "l"(p), "f"(v.x), "f"(v.y), "f"(v.z), "f"(v.w) : "memory");
}

// ---------------- dtype detect (1 warp, parallel) ----------------
__global__ void detect_kernel(const int* __restrict__ ei32) {
    int lane = threadIdx.x & 31;
    int acc = 0;
#pragma unroll
    for (int j = 0; j < 4; j++) acc |= ei32[2 * (lane + 32 * j) + 1];
#pragma unroll
    for (int off = 16; off; off >>= 1) acc |= __shfl_xor_sync(0xffffffffu, acc, off);
    if (lane == 0) g_is64 = (acc == 0) ? 1 : 0;
}

// ---------------- fused: index convert + S1 = x + cnt/sea = 0 -------------------
__global__ void convert_init_kernel(const void* __restrict__ ei,
                                    const float* __restrict__ x) {
    int i = blockIdx.x * blockDim.x + threadIdx.x;
    if (i < 2 * N_EDGES) {
        int v;
        if (g_is64) v = (int)((const long long*)ei)[i];
        else        v = ((const int*)ei)[i];
        g_idx[i] = v;
    }
    if (i < N_NODES * IN_C) g_S1[i] = x[i];
    if (i < N_NODES) { g_cnt[i] = 0.0f; g_sea[i] = 0.0f; }
}

// ---------------- edge gather/scatter: S[dst] += feat[src] (C=64 both layers) ----
template <bool STATS>
__device__ __forceinline__ void scatter_body(const float* __restrict__ feat,
                                             float* __restrict__ S,
                                             const float* __restrict__ ea) {
    const int CH = 16;  // 64 floats / 4
    long long t = (long long)blockIdx.x * blockDim.x + threadIdx.x;
    if (t >= (long long)N_EDGES * CH) return;
    int e = (int)(t / CH);
    int c = (int)(t % CH);
    int s = __ldg(&g_idx[e]);
    int d = __ldg(&g_idx[N_EDGES + e]);
    if (STATS && c == 0) {
        atomicAdd(&g_cnt[d], 1.0f);
        atomicAdd(&g_sea[d], ea[e]);
    }
    float4 v = reinterpret_cast<const float4*>(feat)[(long long)s * CH + c];
    red_add_v4(reinterpret_cast<float*>(
                   &reinterpret_cast<float4*>(S)[(long long)d * CH + c]), v);
}

__global__ void scatter1_kernel(const float* __restrict__ x,
                                const float* __restrict__ ea) {
    scatter_body<true>(x, g_S1, ea);
}
__global__ void scatter2_kernel() {
    scatter_body<false>(g_P, g_S2p, nullptr);
}

// ---------------- node1: 32-node blocks; thread = few-outputs x many-nodes -------
// Stage A: H = relu(cnt*(x·W1_i + b1) + S1·W1_j + sea*w1e); thread = 2o x 16n.
// Stage B: Q = H·W2_i, P = H·W2_j;                          thread = 1o x 16n.
// Smem reads are warp-broadcast (all lanes same node/k); W loads coalesced.
__global__ void __launch_bounds__(128) node1_kernel(const float* __restrict__ x,
                                                    const float* __restrict__ W1,
                                                    const float* __restrict__ b1,
                                                    const float* __restrict__ W2) {
    __shared__ float xs[32][IN_C];
    __shared__ float ss[32][IN_C];
    __shared__ float hs[32][HID_C];
    __shared__ float cs[32], es[32];
    int node0 = blockIdx.x * 32;
    int tid = threadIdx.x;

    // cooperative vectorized load of 32 node rows (guarded for tail block)
    for (int idx = tid; idx < 32 * (IN_C / 4); idx += 128) {
        int n = idx >> 4;
        int k4 = idx & 15;
        int node = node0 + n;
        float4 xv = make_float4(0.f, 0.f, 0.f, 0.f), sv = xv;
        if (node < N_NODES) {
            xv = reinterpret_cast<const float4*>(x)[(long long)node * 16 + k4];
            sv = reinterpret_cast<const float4*>(g_S1)[(long long)node * 16 + k4];
        }
        *reinterpret_cast<float4*>(&xs[n][k4 * 4]) = xv;
        *reinterpret_cast<float4*>(&ss[n][k4 * 4]) = sv;
    }
    if (tid < 32) {
        int node = node0 + tid;
        cs[tid] = (node < N_NODES) ? g_cnt[node] + 1.0f : 1.0f;
        es[tid] = (node < N_NODES) ? g_sea[node] : 0.0f;
    }
    __syncthreads();

    int og = tid & 63;
    int ng = tid >> 6;      // 0 or 1
    int n0 = ng * 16;

    // ---- Stage A: 2 outputs x 16 nodes per thread ----
    {
        int o0 = og * 2;
        float ax0[16], ax1[16], as0[16], as1[16];
#pragma unroll
        for (int n = 0; n < 16; n++) { ax0[n] = ax1[n] = as0[n] = as1[n] = 0.0f; }

        for (int k4 = 0; k4 < IN_C / 4; k4++) {
            int k = k4 * 4;
            float2 wx0 = *reinterpret_cast<const float2*>(&W1[(k + 0) * HID_C + o0]);
            float2 wx1 = *reinterpret_cast<const float2*>(&W1[(k + 1) * HID_C + o0]);
            float2 wx2 = *reinterpret_cast<const float2*>(&W1[(k + 2) * HID_C + o0]);
            float2 wx3 = *reinterpret_cast<const float2*>(&W1[(k + 3) * HID_C + o0]);
            float2 ws0 = *reinterpret_cast<const float2*>(&W1[(IN_C + k + 0) * HID_C + o0]);
            float2 ws1 = *reinterpret_cast<const float2*>(&W1[(IN_C + k + 1) * HID_C + o0]);
            float2 ws2 = *reinterpret_cast<const float2*>(&W1[(IN_C + k + 2) * HID_C + o0]);
            float2 ws3 = *reinterpret_cast<const float2*>(&W1[(IN_C + k + 3) * HID_C + o0]);
#pragma unroll
            for (int n = 0; n < 16; n++) {
                float4 xv = *reinterpret_cast<const float4*>(&xs[n0 + n][k]);  // broadcast
                float4 sv = *reinterpret_cast<const float4*>(&ss[n0 + n][k]);  // broadcast
                ax0[n] += xv.x * wx0.x + xv.y * wx1.x + xv.z * wx2.x + xv.w * wx3.x;
                ax1[n] += xv.x * wx0.y + xv.y * wx1.y + xv.z * wx2.y + xv.w * wx3.y;
                as0[n] += sv.x * ws0.x + sv.y * ws1.x + sv.z * ws2.x + sv.w * ws3.x;
                as1[n] += sv.x * ws0.y + sv.y * ws1.y + sv.z * ws2.y + sv.w * ws3.y;
            }
        }
        float2 bo = *reinterpret_cast<const float2*>(&b1[o0]);
        float2 we = *reinterpret_cast<const float2*>(&W1[2 * IN_C * HID_C + o0]);
#pragma unroll
        for (int n = 0; n < 16; n++) {
            float c = cs[n0 + n], e = es[n0 + n];
            hs[n0 + n][o0 + 0] = fmaxf(c * (ax0[n] + bo.x) + as0[n] + e * we.x, 0.0f);
            hs[n0 + n][o0 + 1] = fmaxf(c * (ax1[n] + bo.y) + as1[n] + e * we.y, 0.0f);
        }
    }
    __syncthreads();

    // ---- Stage B: 1 output x 16 nodes per thread (q and p) over k=128 ----
    {
        int o2 = og;   // 0..63
        float q[16], p[16];
#pragma unroll
        for (int n = 0; n < 16; n++) { q[n] = 0.0f; p[n] = 0.0f; }

        for (int k4 = 0; k4 < HID_C / 4; k4++) {
            int k = k4 * 4;
            float wi0 = W2[(k + 0) * OUT_C + o2];
            float wi1 = W2[(k + 1) * OUT_C + o2];
            float wi2 = W2[(k + 2) * OUT_C + o2];
            float wi3 = W2[(k + 3) * OUT_C + o2];
            float wj0 = W2[(HID_C + k + 0) * OUT_C + o2];
            float wj1 = W2[(HID_C + k + 1) * OUT_C + o2];
            float wj2 = W2[(HID_C + k + 2) * OUT_C + o2];
            float wj3 = W2[(HID_C + k + 3) * OUT_C + o2];
#pragma unroll
            for (int n = 0; n < 16; n++) {
                float4 hv = *reinterpret_cast<const float4*>(&hs[n0 + n][k]);  // broadcast
                q[n] += hv.x * wi0 + hv.y * wi1 + hv.z * wi2 + hv.w * wi3;
                p[n] += hv.x * wj0 + hv.y * wj1 + hv.z * wj2 + hv.w * wj3;
            }
        }
#pragma unroll
        for (int n = 0; n < 16; n++) {
            int node = node0 + n0 + n;
            if (node < N_NODES) {
                long long idx = (long long)node * OUT_C + o2;
                g_Q[idx] = q[n];
                g_P[idx] = p[n];
                g_S2p[idx] = p[n];   // self-loop seed
            }
        }
    }
}

// ---------------- final: layer-2 elementwise epilogue + log_softmax -------------
__global__ void __launch_bounds__(256) final_kernel(const float* __restrict__ W2,
                                                    const float* __restrict__ b2,
                                                    float* __restrict__ out) {
    int warp = (blockIdx.x * blockDim.x + threadIdx.x) >> 5;
    int lane = threadIdx.x & 31;
    if (warp >= N_NODES) return;
    int v = warp;
    float cnt1 = g_cnt[v] + 1.0f;
    float sea  = g_sea[v];
    long long base = (long long)v * OUT_C;
    const float* w2e = &W2[2 * HID_C * OUT_C];

    float v0 = fmaxf(cnt1 * (g_Q[base + lane]      + b2[lane])      + g_S2p[base + lane]      + sea * w2e[lane],      0.0f);
    float v1 = fmaxf(cnt1 * (g_Q[base + lane + 32] + b2[lane + 32]) + g_S2p[base + lane + 32] + sea * w2e[lane + 32], 0.0f);

    float m = fmaxf(v0, v1);
#pragma unroll
    for (int off = 16; off; off >>= 1) m = fmaxf(m, __shfl_xor_sync(0xffffffffu, m, off));
    float s = __expf(v0 - m) + __expf(v1 - m);
#pragma unroll
    for (int off = 16; off; off >>= 1) s += __shfl_xor_sync(0xffffffffu, s, off);
    float ls = logf(s) + m;
    out[base + lane]      = v0 - ls;
    out[base + lane + 32] = v1 - ls;
}

// ---------------- launch ----------------
extern "C" void kernel_launch(void* const* d_in, const int* in_sizes, int n_in,
                              void* d_out, int out_size) {
    const float* x  = (const float*)d_in[0];
    const void*  ei = d_in[1];
    const float* ea = (const float*)d_in[2];
    const float* W1 = (const float*)d_in[3];
    const float* b1 = (const float*)d_in[4];
    const float* W2 = (const float*)d_in[5];
    const float* b2 = (const float*)d_in[6];
    for (int i = 0; i < n_in; i++) {
        switch (in_sizes[i]) {
            case N_NODES * IN_C:          x  = (const float*)d_in[i]; break;
            case 2 * N_EDGES:             ei = d_in[i];               break;
            case N_EDGES:                 ea = (const float*)d_in[i]; break;
            case (2 * IN_C + 1) * HID_C:  W1 = (const float*)d_in[i]; break;
            case HID_C:                   b1 = (const float*)d_in[i]; break;
            case (2 * HID_C + 1) * OUT_C: W2 = (const float*)d_in[i]; break;
            case OUT_C:                   b2 = (const float*)d_in[i]; break;
            default: break;
        }
    }
    float* out = (float*)d_out;

    // 0) dtype detect (parallel); fused convert + init
    detect_kernel<<<1, 32>>>((const int*)ei);
    convert_init_kernel<<<(N_NODES * IN_C + 255) / 256, 256>>>(ei, x);
    // 1) layer-1 neighbor gather/scatter (+ fused degree/edge_attr stats)
    {
        long long work = (long long)N_EDGES * (IN_C / 4);
        scatter1_kernel<<<(unsigned)((work + 255) / 256), 256>>>(x, ea);
    }
    // 2) layer-1 linear + relu (H in smem) + W2 projections -> Q, P, S2p seed
    node1_kernel<<<(N_NODES + 31) / 32, 128>>>(x, W1, b1, W2);
    // 3) layer-2 projected gather/scatter: S2p[dst] += P[src]   (64-wide)
    {
        long long work = (long long)N_EDGES * (OUT_C / 4);
        scatter2_kernel<<<(unsigned)((work + 255) / 256), 256>>>();
    }
    // 4) layer-2 elementwise epilogue + log_softmax
    final_kernel<<<(N_NODES * 32 + 255) / 256, 256>>>(W2, b2, out);
}

// round 17
// speedup vs baseline: 1.1027x; 1.1027x over previous
#include <cuda_runtime.h>

#define N_NODES 50000
#define N_EDGES 800000
#define IN_C    64
#define HID_C   128
#define OUT_C   64

// ---------------- scratch (static device globals; no allocation) ----------------
__device__ __align__(16) float g_S1 [N_NODES * IN_C];   // layer-1 aggregate (incl self)
__device__ __align__(16) float g_P  [N_NODES * OUT_C];  // H·W2_j  (message proj)
__device__ __align__(16) float g_Q  [N_NODES * OUT_C];  // H·W2_i  (self proj)
__device__ __align__(16) float g_S2p[N_NODES * OUT_C];  // layer-2 proj-aggregate
__device__ __align__(16) float g_cnt[N_NODES];          // in-degree (float)
__device__ __align__(16) float g_sea[N_NODES];          // scatter-sum of edge_attr
__device__ __align__(16) int   g_idx[2 * N_EDGES];      // [src(E), dst(E)] as int32
__device__ int g_is64;                                  // edge_index dtype flag

// ---------------- helpers ----------------
__device__ __forceinline__ void red_add_v4(float* p, float4 v) {
    asm volatile("red.global.add.v4.f32 [%0], {%1,%2,%3,%4};"
                 :: "l"(p), "f"(v.x), "f"(v.y), "f"(v.z), "f"(v.w) : "memory");
}

// ---------------- dtype detect (1 warp, parallel) ----------------
__global__ void detect_kernel(const int* __restrict__ ei32) {
    int lane = threadIdx.x & 31;
    int acc = 0;
#pragma unroll
    for (int j = 0; j < 4; j++) acc |= ei32[2 * (lane + 32 * j) + 1];
#pragma unroll
    for (int off = 16; off; off >>= 1) acc |= __shfl_xor_sync(0xffffffffu, acc, off);
    if (lane == 0) g_is64 = (acc == 0) ? 1 : 0;
}

// ---------------- fused: index convert + S1 = x + cnt/sea = 0 -------------------
__global__ void convert_init_kernel(const void* __restrict__ ei,
                                    const float* __restrict__ x) {
    int i = blockIdx.x * blockDim.x + threadIdx.x;
    if (i < 2 * N_EDGES) {
        int v;
        if (g_is64) v = (int)((const long long*)ei)[i];
        else        v = ((const int*)ei)[i];
        g_idx[i] = v;
    }
    if (i < N_NODES * IN_C) g_S1[i] = x[i];
    if (i < N_NODES) { g_cnt[i] = 0.0f; g_sea[i] = 0.0f; }
}

// ---------------- edge gather/scatter: S[dst] += feat[src] (C=64 both layers) ----
template <bool STATS>
__device__ __forceinline__ void scatter_body(const float* __restrict__ feat,
                                             float* __restrict__ S,
                                             const float* __restrict__ ea) {
    const int CH = 16;  // 64 floats / 4
    long long t = (long long)blockIdx.x * blockDim.x + threadIdx.x;
    if (t >= (long long)N_EDGES * CH) return;
    int e = (int)(t / CH);
    int c = (int)(t % CH);
    int s = __ldg(&g_idx[e]);
    int d = __ldg(&g_idx[N_EDGES + e]);
    if (STATS && c == 0) {
        atomicAdd(&g_cnt[d], 1.0f);
        atomicAdd(&g_sea[d], ea[e]);
    }
    float4 v = reinterpret_cast<const float4*>(feat)[(long long)s * CH + c];
    red_add_v4(reinterpret_cast<float*>(
                   &reinterpret_cast<float4*>(S)[(long long)d * CH + c]), v);
}

__global__ void scatter1_kernel(const float* __restrict__ x,
                                const float* __restrict__ ea) {
    scatter_body<true>(x, g_S1, ea);
}
__global__ void scatter2_kernel() {
    scatter_body<false>(g_P, g_S2p, nullptr);
}

// ---------------- node1: concat-operand GEMM (v = [cnt*x ; S1], 128-deep) -------
// Stage A: acc[o] = sum_k v[k]*W1[k][o];  H = relu(acc + cnt*b1 + sea*w1e)
//   thread = 2 outputs x 8 nodes; v in smem (warp-broadcast reads).
// Stage B: Q = H·W2_i, P = H·W2_j; thread = 1 output x 8 nodes (q and p).
__global__ void __launch_bounds__(128) node1_kernel(const float* __restrict__ x,
                                                    const float* __restrict__ W1,
                                                    const float* __restrict__ b1,
                                                    const float* __restrict__ W2) {
    __shared__ float vs[16][2 * IN_C];   // [n][k]: k<64 -> cnt*x, k>=64 -> S1
    __shared__ float hs[16][HID_C];
    __shared__ float cs[16], es[16];
    int node0 = blockIdx.x * 16;
    int tid = threadIdx.x;

    if (tid < 16) {
        cs[tid] = g_cnt[node0 + tid] + 1.0f;
        es[tid] = g_sea[node0 + tid];
    }
    __syncthreads();

    // load v = [cnt*x ; S1]: 16 nodes x 16 k4-chunks, both halves
    for (int idx = tid; idx < 16 * 16; idx += 128) {
        int n = idx >> 4;
        int k4 = idx & 15;
        float c = cs[n];
        float4 xv = reinterpret_cast<const float4*>(x)[(long long)(node0 + n) * 16 + k4];
        float4 sv = reinterpret_cast<const float4*>(g_S1)[(long long)(node0 + n) * 16 + k4];
        xv.x *= c; xv.y *= c; xv.z *= c; xv.w *= c;
        *reinterpret_cast<float4*>(&vs[n][k4 * 4]) = xv;
        *reinterpret_cast<float4*>(&vs[n][IN_C + k4 * 4]) = sv;
    }
    __syncthreads();

    int og = tid & 63;
    int ng = tid >> 6;      // 0 or 1
    int n0 = ng * 8;

    // ---- Stage A: 2 outputs x 8 nodes per thread over k=128 ----
    {
        int o0 = og * 2;
        float a0[8], a1[8];
#pragma unroll
        for (int n = 0; n < 8; n++) { a0[n] = 0.0f; a1[n] = 0.0f; }

        for (int k4 = 0; k4 < (2 * IN_C) / 4; k4++) {
            int k = k4 * 4;
            float2 w0 = *reinterpret_cast<const float2*>(&W1[(k + 0) * HID_C + o0]);
            float2 w1 = *reinterpret_cast<const float2*>(&W1[(k + 1) * HID_C + o0]);
            float2 w2 = *reinterpret_cast<const float2*>(&W1[(k + 2) * HID_C + o0]);
            float2 w3 = *reinterpret_cast<const float2*>(&W1[(k + 3) * HID_C + o0]);
#pragma unroll
            for (int n = 0; n < 8; n++) {
                float4 v = *reinterpret_cast<const float4*>(&vs[n0 + n][k]);  // broadcast
                a0[n] += v.x * w0.x + v.y * w1.x + v.z * w2.x + v.w * w3.x;
                a1[n] += v.x * w0.y + v.y * w1.y + v.z * w2.y + v.w * w3.y;
            }
        }
        float2 bo = *reinterpret_cast<const float2*>(&b1[o0]);
        float2 we = *reinterpret_cast<const float2*>(&W1[2 * IN_C * HID_C + o0]);
#pragma unroll
        for (int n = 0; n < 8; n++) {
            float c = cs[n0 + n], e = es[n0 + n];
            hs[n0 + n][o0 + 0] = fmaxf(a0[n] + c * bo.x + e * we.x, 0.0f);
            hs[n0 + n][o0 + 1] = fmaxf(a1[n] + c * bo.y + e * we.y, 0.0f);
        }
    }
    __syncthreads();

    // ---- Stage B: 1 output x 8 nodes per thread (q and p) over k=128 ----
    {
        int o2 = og;   // 0..63
        float q[8], p[8];
#pragma unroll
        for (int n = 0; n < 8; n++) { q[n] = 0.0f; p[n] = 0.0f; }

        for (int k4 = 0; k4 < HID_C / 4; k4++) {
            int k = k4 * 4;
            float wi0 = W2[(k + 0) * OUT_C + o2];
            float wi1 = W2[(k + 1) * OUT_C + o2];
            float wi2 = W2[(k + 2) * OUT_C + o2];
            float wi3 = W2[(k + 3) * OUT_C + o2];
            float wj0 = W2[(HID_C + k + 0) * OUT_C + o2];
            float wj1 = W2[(HID_C + k + 1) * OUT_C + o2];
            float wj2 = W2[(HID_C + k + 2) * OUT_C + o2];
            float wj3 = W2[(HID_C + k + 3) * OUT_C + o2];
#pragma unroll
            for (int n = 0; n < 8; n++) {
                float4 hv = *reinterpret_cast<const float4*>(&hs[n0 + n][k]);  // broadcast
                q[n] += hv.x * wi0 + hv.y * wi1 + hv.z * wi2 + hv.w * wi3;
                p[n] += hv.x * wj0 + hv.y * wj1 + hv.z * wj2 + hv.w * wj3;
            }
        }
#pragma unroll
        for (int n = 0; n < 8; n++) {
            long long idx = (long long)(node0 + n0 + n) * OUT_C + o2;
            g_Q[idx] = q[n];
            g_P[idx] = p[n];
            g_S2p[idx] = p[n];   // self-loop seed
        }
    }
}

// ---------------- final: layer-2 elementwise epilogue + log_softmax -------------
__global__ void __launch_bounds__(256) final_kernel(const float* __restrict__ W2,
                                                    const float* __restrict__ b2,
                                                    float* __restrict__ out) {
    int warp = (blockIdx.x * blockDim.x + threadIdx.x) >> 5;
    int lane = threadIdx.x & 31;
    if (warp >= N_NODES) return;
    int v = warp;
    float cnt1 = g_cnt[v] + 1.0f;
    float sea  = g_sea[v];
    long long base = (long long)v * OUT_C;
    const float* w2e = &W2[2 * HID_C * OUT_C];

    float v0 = fmaxf(cnt1 * (g_Q[base + lane]      + b2[lane])      + g_S2p[base + lane]      + sea * w2e[lane],      0.0f);
    float v1 = fmaxf(cnt1 * (g_Q[base + lane + 32] + b2[lane + 32]) + g_S2p[base + lane + 32] + sea * w2e[lane + 32], 0.0f);

    float m = fmaxf(v0, v1);
#pragma unroll
    for (int off = 16; off; off >>= 1) m = fmaxf(m, __shfl_xor_sync(0xffffffffu, m, off));
    float s = __expf(v0 - m) + __expf(v1 - m);
#pragma unroll
    for (int off = 16; off; off >>= 1) s += __shfl_xor_sync(0xffffffffu, s, off);
    float ls = logf(s) + m;
    out[base + lane]      = v0 - ls;
    out[base + lane + 32] = v1 - ls;
}

// ---------------- launch ----------------
extern "C" void kernel_launch(void* const* d_in, const int* in_sizes, int n_in,
                              void* d_out, int out_size) {
    const float* x  = (const float*)d_in[0];
    const void*  ei = d_in[1];
    const float* ea = (const float*)d_in[2];
    const float* W1 = (const float*)d_in[3];
    const float* b1 = (const float*)d_in[4];
    const float* W2 = (const float*)d_in[5];
    const float* b2 = (const float*)d_in[6];
    for (int i = 0; i < n_in; i++) {
        switch (in_sizes[i]) {
            case N_NODES * IN_C:          x  = (const float*)d_in[i]; break;
            case 2 * N_EDGES:             ei = d_in[i];               break;
            case N_EDGES:                 ea = (const float*)d_in[i]; break;
            case (2 * IN_C + 1) * HID_C:  W1 = (const float*)d_in[i]; break;
            case HID_C:                   b1 = (const float*)d_in[i]; break;
            case (2 * HID_C + 1) * OUT_C: W2 = (const float*)d_in[i]; break;
            case OUT_C:                   b2 = (const float*)d_in[i]; break;
            default: break;
        }
    }
    float* out = (float*)d_out;

    // 0) dtype detect (parallel); fused convert + init
    detect_kernel<<<1, 32>>>((const int*)ei);
    convert_init_kernel<<<(N_NODES * IN_C + 255) / 256, 256>>>(ei, x);
    // 1) layer-1 neighbor gather/scatter (+ fused degree/edge_attr stats)
    {
        long long work = (long long)N_EDGES * (IN_C / 4);
        scatter1_kernel<<<(unsigned)((work + 255) / 256), 256>>>(x, ea);
    }
    // 2) layer-1 concat-GEMM + relu (H in smem) + W2 projections -> Q, P, S2p seed
    node1_kernel<<<N_NODES / 16, 128>>>(x, W1, b1, W2);
    // 3) layer-2 projected gather/scatter: S2p[dst] += P[src]   (64-wide)
    {
        long long work = (long long)N_EDGES * (OUT_C / 4);
        scatter2_kernel<<<(unsigned)((work + 255) / 256), 256>>>();
    }
    // 4) layer-2 elementwise epilogue + log_softmax
    final_kernel<<<(N_NODES * 32 + 255) / 256, 256>>>(W2, b2, out);
}